// round 14
// baseline (speedup 1.0000x reference)
#include <cuda_runtime.h>
#include <cuda_fp16.h>
#include <cuda_bf16.h>
#include <cstdint>

// ===================== problem shape (fixed) =====================
#define MDIM 8192   // B*S = 4*2048
#define NDIM 4096   // DOUT
#define KDIM 4096   // DIN

// ===================== GEMM tiling (R11/R5 converged config) =============
#define BM 128
#define BN 256
#define BK 64
#define STG 3
#define NKT (KDIM / BK)          // 64 kt per tile
#define NKS (BK / 16)            // 4 k-chunks per stage
#define SKEW 8
#define ROWH (BK + SKEW)         // 72 halves per smem row
#define ROWB (ROWH * 2)          // 144 bytes per smem row
#define STAGE_BYTES ((BM + BN) * ROWB)   // 55296
#define SMEM_TOTAL (STG * STAGE_BYTES)   // 165888
#define NTHREADS 256             // 8 warps: 2(m) x 4(n) grid of 64x64 tiles
#define NTILES 1024              // (NDIM/BN) * (MDIM/BM) = 16 * 64
#define GRIDSZ 148               // persistent CTAs; ceil(1024/148)=7 = today's wave count

// ===================== scratch (static device globals; no allocation) ====
__device__ __align__(256) __half g_Xh[(size_t)MDIM * KDIM];   // 64 MiB
__device__ __align__(256) __half g_Wh[(size_t)NDIM * KDIM];   // 32 MiB

// ===================== merged prep kernel (R13 exact) ====================
#define PREP_TPB 256
#define NX8 ((MDIM * KDIM) / 8)
#define NW8 ((NDIM * KDIM) / 8)
#define NBX (NX8 / PREP_TPB)
#define NBW (NW8 / PREP_TPB)

__global__ void prep_kernel(const float* __restrict__ x,
                            const void* __restrict__ w) {
    const int b = blockIdx.x;
    if (b < NBX) {
        const int i = b * PREP_TPB + threadIdx.x;
        float4 v0 = reinterpret_cast<const float4*>(x)[2 * i];
        float4 v1 = reinterpret_cast<const float4*>(x)[2 * i + 1];
        __half2 h0 = __floats2half2_rn(v0.x, v0.y);
        __half2 h1 = __floats2half2_rn(v0.z, v0.w);
        __half2 h2 = __floats2half2_rn(v1.x, v1.y);
        __half2 h3 = __floats2half2_rn(v1.z, v1.w);
        uint4 u;
        u.x = *reinterpret_cast<uint32_t*>(&h0);
        u.y = *reinterpret_cast<uint32_t*>(&h1);
        u.z = *reinterpret_cast<uint32_t*>(&h2);
        u.w = *reinterpret_cast<uint32_t*>(&h3);
        reinterpret_cast<uint4*>(g_Xh)[i] = u;
        return;
    }
    // w path: in-block dtype probe on fixed 64 leading elements
    int bad_i32 = 0, bad_f32 = 0, bad_bf16 = 0;
    if (threadIdx.x < 64) {
        const int k = threadIdx.x;
        int vi = ((const int*)w)[k];
        bad_i32 = (vi < -127 || vi > 127);
        float vf = ((const float*)w)[k];
        bad_f32 = !(isfinite(vf) && fabsf(vf) <= 127.f && vf == rintf(vf));
        float vb = __bfloat162float(((const __nv_bfloat16*)w)[k]);
        bad_bf16 = !(isfinite(vb) && fabsf(vb) <= 127.f && vb == rintf(vb));
    }
    bad_i32  = __syncthreads_or(bad_i32);
    bad_f32  = __syncthreads_or(bad_f32);
    bad_bf16 = __syncthreads_or(bad_bf16);
    int t = 0;
    if (!bad_i32)       t = 1;
    else if (!bad_f32)  t = 2;
    else if (!bad_bf16) t = 3;

    const int j = (b - NBX) * PREP_TPB + threadIdx.x;
    float f[8];
    if (t == 1) {
        int4 v0 = reinterpret_cast<const int4*>(w)[2 * j];
        int4 v1 = reinterpret_cast<const int4*>(w)[2 * j + 1];
        f[0] = (float)v0.x; f[1] = (float)v0.y; f[2] = (float)v0.z; f[3] = (float)v0.w;
        f[4] = (float)v1.x; f[5] = (float)v1.y; f[6] = (float)v1.z; f[7] = (float)v1.w;
    } else if (t == 2) {
        float4 v0 = reinterpret_cast<const float4*>(w)[2 * j];
        float4 v1 = reinterpret_cast<const float4*>(w)[2 * j + 1];
        f[0] = v0.x; f[1] = v0.y; f[2] = v0.z; f[3] = v0.w;
        f[4] = v1.x; f[5] = v1.y; f[6] = v1.z; f[7] = v1.w;
    } else if (t == 3) {
        const __nv_bfloat162* p = reinterpret_cast<const __nv_bfloat162*>(w);
        #pragma unroll
        for (int k = 0; k < 4; k++) {
            __nv_bfloat162 v = p[4 * j + k];
            f[2 * k]     = __bfloat162float(v.x);
            f[2 * k + 1] = __bfloat162float(v.y);
        }
    } else {
        const char4* p = reinterpret_cast<const char4*>(w);
        #pragma unroll
        for (int k = 0; k < 2; k++) {
            char4 v = p[2 * j + k];
            f[4 * k]     = (float)v.x; f[4 * k + 1] = (float)v.y;
            f[4 * k + 2] = (float)v.z; f[4 * k + 3] = (float)v.w;
        }
    }
    __half2 h0 = __floats2half2_rn(f[0], f[1]);
    __half2 h1 = __floats2half2_rn(f[2], f[3]);
    __half2 h2 = __floats2half2_rn(f[4], f[5]);
    __half2 h3 = __floats2half2_rn(f[6], f[7]);
    uint4 u;
    u.x = *reinterpret_cast<uint32_t*>(&h0);
    u.y = *reinterpret_cast<uint32_t*>(&h1);
    u.z = *reinterpret_cast<uint32_t*>(&h2);
    u.w = *reinterpret_cast<uint32_t*>(&h3);
    reinterpret_cast<uint4*>(g_Wh)[j] = u;
}

// ===================== helpers =====================
__device__ __forceinline__ uint32_t smem_u32(const void* p) {
    uint32_t a;
    asm("{ .reg .u64 t; cvta.to.shared.u64 t, %1; cvt.u32.u64 %0, t; }" : "=r"(a) : "l"(p));
    return a;
}
__device__ __forceinline__ void cp16(uint32_t s, const void* g) {
    asm volatile("cp.async.cg.shared.global [%0], [%1], 16;" :: "r"(s), "l"(g) : "memory");
}
__device__ __forceinline__ void ldm_x4(uint32_t& r0, uint32_t& r1, uint32_t& r2, uint32_t& r3,
                                       uint32_t addr) {
    asm volatile("ldmatrix.sync.aligned.m8n8.x4.shared.b16 {%0,%1,%2,%3}, [%4];"
                 : "=r"(r0), "=r"(r1), "=r"(r2), "=r"(r3) : "r"(addr));
}
__device__ __forceinline__ void mma16816(float* c, const uint32_t* a, uint32_t b0, uint32_t b1) {
    asm volatile(
        "mma.sync.aligned.m16n8k16.row.col.f32.f16.f16.f32 "
        "{%0,%1,%2,%3}, {%4,%5,%6,%7}, {%8,%9}, {%0,%1,%2,%3};"
        : "+f"(c[0]), "+f"(c[1]), "+f"(c[2]), "+f"(c[3])
        : "r"(a[0]), "r"(a[1]), "r"(a[2]), "r"(a[3]), "r"(b0), "r"(b1));
}

// ===================== persistent GEMM kernel ============================
// 148 persistent CTAs, each looping tiles t = bid + w*148. Flat global-kt
// pipeline: the cp.async ring and ks schedule run continuously ACROSS tile
// boundaries (loads at tile end already target the next tile's k=0 slabs),
// so tile transitions pay no prologue drain; the per-tile epilogue overlaps
// with the next tile's in-flight loads.
__global__ __launch_bounds__(NTHREADS, 1)
void gemm_hmma_kernel(const float* __restrict__ scale,
                      const float* __restrict__ bias,
                      float* __restrict__ out) {
    extern __shared__ char smem[];
    const uint32_t sbase = smem_u32(smem);

    const int tid    = threadIdx.x;
    const int lane   = tid & 31;
    const int wid    = tid >> 5;
    const int warp_m = wid >> 2;        // 0..1 -> 64-row slab
    const int warp_n = wid & 3;         // 0..3 -> 64-col slab
    const int bid    = blockIdx.x;

    const int ntiles = (NTILES - bid + GRIDSZ - 1) / GRIDSZ;  // 7 or 6
    const int Q      = ntiles * NKT;                          // global kt count

    // per-thread stage-fill offsets (12 chunks): precompute row/col
    // i<4 -> A rows (0..127), i>=4 -> B rows (0..255)
    // load_stage(q): tile t = bid + (q>>6)*GRIDSZ, kofs = (q&63)*BK
    auto load_stage = [&](int q) {
        const int t  = bid + (q >> 6) * GRIDSZ;
        const int kofs = (q & 63) * BK;
        const uint32_t st = sbase + (uint32_t)(q % STG) * STAGE_BYTES;
        const __half* gA = g_Xh + (size_t)((t >> 4) * BM) * KDIM;
        const __half* gB = g_Wh + (size_t)((t & 15) * BN) * KDIM;
        #pragma unroll
        for (int i = 0; i < 12; i++) {
            const int ch = tid + i * NTHREADS;    // 0..3071
            const int row = ch >> 3, col = ch & 7;
            const __half* g = (i < 4) ? (gA + (size_t)row * KDIM)
                                      : (gB + (size_t)(row - BM) * KDIM);
            cp16(st + row * ROWB + col * 16, g + kofs + col * 8);
        }
    };

    // ldmatrix per-lane row/col assignment
    const int lrow = lane & 15;
    const int lcol = (lane >> 4) << 3;

    uint32_t fa[2][4][4];
    uint32_t fb[2][4][4];
    float acc[4][8][4];
    #pragma unroll
    for (int mi = 0; mi < 4; mi++)
        #pragma unroll
        for (int ni = 0; ni < 8; ni++)
            #pragma unroll
            for (int e = 0; e < 4; e++) acc[mi][ni][e] = 0.f;

    const uint32_t a_off = (warp_m * 64 + lrow) * ROWB + lcol * 2;
    const uint32_t b_off = (BM + warp_n * 64 + lrow) * ROWB + lcol * 2;

    auto load_frag = [&](int buf, uint32_t stg, int ks) {
        const uint32_t aB = stg + a_off + ks * 32;
        const uint32_t bB = stg + b_off + ks * 32;
        #pragma unroll
        for (int mi = 0; mi < 4; mi++)
            ldm_x4(fa[buf][mi][0], fa[buf][mi][1], fa[buf][mi][2], fa[buf][mi][3],
                   aB + mi * 16 * ROWB);
        #pragma unroll
        for (int nb = 0; nb < 4; nb++)
            ldm_x4(fb[buf][nb][0], fb[buf][nb][1], fb[buf][nb][2], fb[buf][nb][3],
                   bB + nb * 16 * ROWB);
    };

    auto do_mma = [&](int buf) {
        #pragma unroll
        for (int mi = 0; mi < 4; mi++) {
            #pragma unroll
            for (int ni = 0; ni < 8; ni++) {
                const int nb = ni >> 1;
                if (ni & 1) mma16816(acc[mi][ni], fa[buf][mi], fb[buf][nb][1], fb[buf][nb][3]);
                else        mma16816(acc[mi][ni], fa[buf][mi], fb[buf][nb][0], fb[buf][nb][2]);
            }
        }
    };

    // ---- prologue: fill stages for q=0,1, load first fragment chunk ----
    load_stage(0);
    asm volatile("cp.async.commit_group;" ::: "memory");
    load_stage(1);
    asm volatile("cp.async.commit_group;" ::: "memory");
    asm volatile("cp.async.wait_group 1;" ::: "memory");
    __syncthreads();
    load_frag(0, sbase, 0);

    const int groupID = lane >> 2;
    const int tig     = lane & 3;

    // ---- flat mainloop over global kt ----
    for (int q = 0; q < Q; q++) {
        const uint32_t stage_cur = sbase + (uint32_t)(q % STG) * STAGE_BYTES;
        const uint32_t stage_nxt = sbase + (uint32_t)((q + 1) % STG) * STAGE_BYTES;
        #pragma unroll
        for (int ks = 0; ks < NKS; ks++) {
            const int cur = ks & 1, nxt = cur ^ 1;
            if (ks == NKS - 1) {
                asm volatile("cp.async.wait_group 1;" ::: "memory");
                __syncthreads();
                if (q + 1 < Q) load_frag(nxt, stage_nxt, 0);
            } else {
                load_frag(nxt, stage_cur, ks + 1);
            }
            if (ks == 0) {
                if (q + 2 < Q) load_stage(q + 2);
                asm volatile("cp.async.commit_group;" ::: "memory");
            }
            do_mma(cur);
        }

        // ---- per-tile epilogue (overlaps next tile's in-flight loads) ----
        if ((q & 63) == 63) {
            const int t  = bid + (q >> 6) * GRIDSZ;
            const int m0 = (t >> 4) * BM;
            const int n0 = (t & 15) * BN;
            const int ncol0 = n0 + warp_n * 64;

            float2 sc2[8], bi2[8];
            #pragma unroll
            for (int ni = 0; ni < 8; ni++) {
                const int gn = ncol0 + ni * 8 + tig * 2;
                sc2[ni] = *reinterpret_cast<const float2*>(scale + gn);
                bi2[ni] = *reinterpret_cast<const float2*>(bias + gn);
            }
            #pragma unroll
            for (int mi = 0; mi < 4; mi++) {
                const int gm = m0 + warp_m * 64 + mi * 16 + groupID;
                float* r0 = out + (size_t)gm * NDIM;
                float* r1 = r0 + (size_t)8 * NDIM;
                #pragma unroll
                for (int ni = 0; ni < 8; ni++) {
                    const int gn = ncol0 + ni * 8 + tig * 2;
                    float2 v0, v1;
                    v0.x = fmaf(acc[mi][ni][0], sc2[ni].x, bi2[ni].x);
                    v0.y = fmaf(acc[mi][ni][1], sc2[ni].y, bi2[ni].y);
                    v1.x = fmaf(acc[mi][ni][2], sc2[ni].x, bi2[ni].x);
                    v1.y = fmaf(acc[mi][ni][3], sc2[ni].y, bi2[ni].y);
                    *reinterpret_cast<float2*>(r0 + gn) = v0;
                    *reinterpret_cast<float2*>(r1 + gn) = v1;
                    acc[mi][ni][0] = 0.f; acc[mi][ni][1] = 0.f;
                    acc[mi][ni][2] = 0.f; acc[mi][ni][3] = 0.f;
                }
            }
        }
    }
}

// ===================== host side =====================
extern "C" void kernel_launch(void* const* d_in, const int* in_sizes, int n_in,
                              void* d_out, int out_size) {
    const float* x   = (const float*)d_in[0];
    const void*  w   = d_in[1];
    const float* sc  = (const float*)d_in[2];
    const float* bi  = (const float*)d_in[3];
    float*       out = (float*)d_out;

    // single merged prep launch: x-convert + (self-probing) w-convert
    prep_kernel<<<NBX + NBW, PREP_TPB>>>(x, w);

    cudaFuncSetAttribute(gemm_hmma_kernel,
                         cudaFuncAttributeMaxDynamicSharedMemorySize, SMEM_TOTAL);

    gemm_hmma_kernel<<<GRIDSZ, NTHREADS, SMEM_TOTAL>>>(sc, bi, out);
}

// round 15
// speedup vs baseline: 1.3865x; 1.3865x over previous
#include <cuda_runtime.h>
#include <cuda_fp16.h>
#include <cuda_bf16.h>
#include <cstdint>

// ===================== problem shape (fixed) =====================
#define MDIM 8192   // B*S = 4*2048
#define NDIM 4096   // DOUT
#define KDIM 4096   // DIN

// ===================== GEMM tiling (R13 converged config) ================
#define BM 128
#define BN 256
#define BK 64
#define STG 3
#define NKT (KDIM / BK)          // 64 mainloop iterations
#define NKS (BK / 16)            // 4 k-chunks per stage
#define SKEW 8
#define ROWH (BK + SKEW)         // 72 halves per smem row
#define ROWB (ROWH * 2)          // 144 bytes per smem row
#define STAGE_BYTES ((BM + BN) * ROWB)   // 55296
#define SMEM_TOTAL (STG * STAGE_BYTES)   // 165888
#define NTHREADS 256             // 8 warps: 2(m) x 4(n) grid of 64x64 tiles

// ===================== scratch (static device globals; no allocation) ====
__device__ __align__(256) __half g_Xh[(size_t)MDIM * KDIM];   // 64 MiB
__device__ __align__(256) __half g_Wh[(size_t)NDIM * KDIM];   // 32 MiB

// ===================== merged prep kernel (R13 exact) ====================
#define PREP_TPB 256
#define NX8 ((MDIM * KDIM) / 8)
#define NW8 ((NDIM * KDIM) / 8)
#define NBX (NX8 / PREP_TPB)
#define NBW (NW8 / PREP_TPB)

__global__ void prep_kernel(const float* __restrict__ x,
                            const void* __restrict__ w) {
    const int b = blockIdx.x;
    if (b < NBX) {
        const int i = b * PREP_TPB + threadIdx.x;
        float4 v0 = reinterpret_cast<const float4*>(x)[2 * i];
        float4 v1 = reinterpret_cast<const float4*>(x)[2 * i + 1];
        __half2 h0 = __floats2half2_rn(v0.x, v0.y);
        __half2 h1 = __floats2half2_rn(v0.z, v0.w);
        __half2 h2 = __floats2half2_rn(v1.x, v1.y);
        __half2 h3 = __floats2half2_rn(v1.z, v1.w);
        uint4 u;
        u.x = *reinterpret_cast<uint32_t*>(&h0);
        u.y = *reinterpret_cast<uint32_t*>(&h1);
        u.z = *reinterpret_cast<uint32_t*>(&h2);
        u.w = *reinterpret_cast<uint32_t*>(&h3);
        reinterpret_cast<uint4*>(g_Xh)[i] = u;
        return;
    }
    // w path: in-block dtype probe on fixed 64 leading elements
    int bad_i32 = 0, bad_f32 = 0, bad_bf16 = 0;
    if (threadIdx.x < 64) {
        const int k = threadIdx.x;
        int vi = ((const int*)w)[k];
        bad_i32 = (vi < -127 || vi > 127);
        float vf = ((const float*)w)[k];
        bad_f32 = !(isfinite(vf) && fabsf(vf) <= 127.f && vf == rintf(vf));
        float vb = __bfloat162float(((const __nv_bfloat16*)w)[k]);
        bad_bf16 = !(isfinite(vb) && fabsf(vb) <= 127.f && vb == rintf(vb));
    }
    bad_i32  = __syncthreads_or(bad_i32);
    bad_f32  = __syncthreads_or(bad_f32);
    bad_bf16 = __syncthreads_or(bad_bf16);
    int t = 0;                    // 0=int8, 1=int32, 2=float32, 3=bf16
    if (!bad_i32)       t = 1;
    else if (!bad_f32)  t = 2;
    else if (!bad_bf16) t = 3;

    const int j = (b - NBX) * PREP_TPB + threadIdx.x;
    float f[8];
    if (t == 1) {                     // int32 promotion (expected path)
        int4 v0 = reinterpret_cast<const int4*>(w)[2 * j];
        int4 v1 = reinterpret_cast<const int4*>(w)[2 * j + 1];
        f[0] = (float)v0.x; f[1] = (float)v0.y; f[2] = (float)v0.z; f[3] = (float)v0.w;
        f[4] = (float)v1.x; f[5] = (float)v1.y; f[6] = (float)v1.z; f[7] = (float)v1.w;
    } else if (t == 2) {              // float32
        float4 v0 = reinterpret_cast<const float4*>(w)[2 * j];
        float4 v1 = reinterpret_cast<const float4*>(w)[2 * j + 1];
        f[0] = v0.x; f[1] = v0.y; f[2] = v0.z; f[3] = v0.w;
        f[4] = v1.x; f[5] = v1.y; f[6] = v1.z; f[7] = v1.w;
    } else if (t == 3) {              // bf16
        const __nv_bfloat162* p = reinterpret_cast<const __nv_bfloat162*>(w);
        #pragma unroll
        for (int k = 0; k < 4; k++) {
            __nv_bfloat162 v = p[4 * j + k];
            f[2 * k]     = __bfloat162float(v.x);
            f[2 * k + 1] = __bfloat162float(v.y);
        }
    } else {                          // genuine int8
        const char4* p = reinterpret_cast<const char4*>(w);
        #pragma unroll
        for (int k = 0; k < 2; k++) {
            char4 v = p[2 * j + k];
            f[4 * k]     = (float)v.x; f[4 * k + 1] = (float)v.y;
            f[4 * k + 2] = (float)v.z; f[4 * k + 3] = (float)v.w;
        }
    }
    __half2 h0 = __floats2half2_rn(f[0], f[1]);
    __half2 h1 = __floats2half2_rn(f[2], f[3]);
    __half2 h2 = __floats2half2_rn(f[4], f[5]);
    __half2 h3 = __floats2half2_rn(f[6], f[7]);
    uint4 u;
    u.x = *reinterpret_cast<uint32_t*>(&h0);
    u.y = *reinterpret_cast<uint32_t*>(&h1);
    u.z = *reinterpret_cast<uint32_t*>(&h2);
    u.w = *reinterpret_cast<uint32_t*>(&h3);
    reinterpret_cast<uint4*>(g_Wh)[j] = u;
}

// ===================== helpers =====================
__device__ __forceinline__ uint32_t smem_u32(const void* p) {
    uint32_t a;
    asm("{ .reg .u64 t; cvta.to.shared.u64 t, %1; cvt.u32.u64 %0, t; }" : "=r"(a) : "l"(p));
    return a;
}
__device__ __forceinline__ void cp16(uint32_t s, const void* g) {
    asm volatile("cp.async.cg.shared.global [%0], [%1], 16;" :: "r"(s), "l"(g) : "memory");
}
__device__ __forceinline__ void ldm_x4(uint32_t& r0, uint32_t& r1, uint32_t& r2, uint32_t& r3,
                                       uint32_t addr) {
    asm volatile("ldmatrix.sync.aligned.m8n8.x4.shared.b16 {%0,%1,%2,%3}, [%4];"
                 : "=r"(r0), "=r"(r1), "=r"(r2), "=r"(r3) : "r"(addr));
}
__device__ __forceinline__ void mma16816(float* c, const uint32_t* a, uint32_t b0, uint32_t b1) {
    asm volatile(
        "mma.sync.aligned.m16n8k16.row.col.f32.f16.f16.f32 "
        "{%0,%1,%2,%3}, {%4,%5,%6,%7}, {%8,%9}, {%0,%1,%2,%3};"
        : "+f"(c[0]), "+f"(c[1]), "+f"(c[2]), "+f"(c[3])
        : "r"(a[0]), "r"(a[1]), "r"(a[2]), "r"(a[3]), "r"(b0), "r"(b1));
}

// ===================== GEMM kernel (R13 + rotated stage offsets) =========
// CTA 128x256x64, 3-stage cp.async pipeline, register double-buffered
// fragments. Stage offsets maintained by register rotation (no % in loop).
__global__ __launch_bounds__(NTHREADS, 1)
void gemm_hmma_kernel(const float* __restrict__ scale,
                      const float* __restrict__ bias,
                      float* __restrict__ out) {
    extern __shared__ char smem[];
    const uint32_t sbase = smem_u32(smem);

    const int tid    = threadIdx.x;
    const int lane   = tid & 31;
    const int wid    = tid >> 5;
    const int warp_m = wid >> 2;        // 0..1 -> 64-row slab
    const int warp_n = wid & 3;         // 0..3 -> 64-col slab
    const int n0     = blockIdx.x * BN;
    const int m0     = blockIdx.y * BM;

    const __half* gA = g_Xh + (size_t)(m0) * KDIM;
    const __half* gB = g_Wh + (size_t)(n0) * KDIM;

    // stage fill: 384 rows x 8 chunks of 16B = 3072 chunks; 12 per thread.
    // i<4 -> A rows (0..127), i>=4 -> B rows (0..255).
    auto load_stage = [&](uint32_t st, int kt) {
        const int kofs = kt * BK;
        #pragma unroll
        for (int i = 0; i < 12; i++) {
            const int ch = tid + i * NTHREADS;    // 0..3071
            const int row = ch >> 3, col = ch & 7;
            const __half* g = (i < 4) ? (gA + (size_t)row * KDIM)
                                      : (gB + (size_t)(row - BM) * KDIM);
            cp16(st + row * ROWB + col * 16, g + kofs + col * 8);
        }
    };

    // ldmatrix per-lane row/col assignment
    const int lrow = lane & 15;               // row within 16-row block
    const int lcol = (lane >> 4) << 3;        // 0 or 8 halves

    uint32_t fa[2][4][4];
    uint32_t fb[2][4][4];
    float acc[4][8][4];
    #pragma unroll
    for (int mi = 0; mi < 4; mi++)
        #pragma unroll
        for (int ni = 0; ni < 8; ni++)
            #pragma unroll
            for (int e = 0; e < 4; e++) acc[mi][ni][e] = 0.f;

    const uint32_t a_off = (warp_m * 64 + lrow) * ROWB + lcol * 2;
    const uint32_t b_off = (BM + warp_n * 64 + lrow) * ROWB + lcol * 2;

    auto load_frag = [&](int buf, uint32_t stg, int ks) {
        const uint32_t aB = stg + a_off + ks * 32;
        const uint32_t bB = stg + b_off + ks * 32;
        #pragma unroll
        for (int mi = 0; mi < 4; mi++)
            ldm_x4(fa[buf][mi][0], fa[buf][mi][1], fa[buf][mi][2], fa[buf][mi][3],
                   aB + mi * 16 * ROWB);
        #pragma unroll
        for (int nb = 0; nb < 4; nb++)
            ldm_x4(fb[buf][nb][0], fb[buf][nb][1], fb[buf][nb][2], fb[buf][nb][3],
                   bB + nb * 16 * ROWB);
    };

    auto do_mma = [&](int buf) {
        #pragma unroll
        for (int mi = 0; mi < 4; mi++) {
            #pragma unroll
            for (int ni = 0; ni < 8; ni++) {
                const int nb = ni >> 1;
                if (ni & 1) mma16816(acc[mi][ni], fa[buf][mi], fb[buf][nb][1], fb[buf][nb][3]);
                else        mma16816(acc[mi][ni], fa[buf][mi], fb[buf][nb][0], fb[buf][nb][2]);
            }
        }
    };

    // ---- prologue: fill 2 stages, load first fragment chunk ----
    load_stage(sbase, 0);
    asm volatile("cp.async.commit_group;" ::: "memory");
    load_stage(sbase + STAGE_BYTES, 1);
    asm volatile("cp.async.commit_group;" ::: "memory");
    asm volatile("cp.async.wait_group 1;" ::: "memory");
    __syncthreads();
    load_frag(0, sbase, 0);

    // rotating stage offsets: cur = kt%3, nxt = (kt+1)%3, ld = (kt+2)%3
    uint32_t st_cur = sbase;
    uint32_t st_nxt = sbase + STAGE_BYTES;
    uint32_t st_ld  = sbase + 2 * STAGE_BYTES;

    // ---- mainloop ----
    for (int kt = 0; kt < NKT; kt++) {
        #pragma unroll
        for (int ks = 0; ks < NKS; ks++) {
            const int cur = ks & 1, nxt = cur ^ 1;
            if (ks == NKS - 1) {
                // make stage kt+1 readable, then prefetch its first fragments
                asm volatile("cp.async.wait_group 1;" ::: "memory");
                __syncthreads();
                if (kt + 1 < NKT) load_frag(nxt, st_nxt, 0);
            } else {
                load_frag(nxt, st_cur, ks + 1);
            }
            if (ks == 0) {
                if (kt + STG - 1 < NKT)
                    load_stage(st_ld, kt + STG - 1);
                asm volatile("cp.async.commit_group;" ::: "memory");
            }
            do_mma(cur);
        }
        // rotate stage ring
        const uint32_t tmp = st_cur;
        st_cur = st_nxt; st_nxt = st_ld; st_ld = tmp;
    }

    // ---- epilogue: y = acc * scale[n] + bias[n] ----
    const int groupID = lane >> 2;
    const int tig     = lane & 3;
    const int ncol0   = n0 + warp_n * 64;

    float2 sc2[8], bi2[8];
    #pragma unroll
    for (int ni = 0; ni < 8; ni++) {
        const int gn = ncol0 + ni * 8 + tig * 2;
        sc2[ni] = *reinterpret_cast<const float2*>(scale + gn);
        bi2[ni] = *reinterpret_cast<const float2*>(bias + gn);
    }

    #pragma unroll
    for (int mi = 0; mi < 4; mi++) {
        const int gm = m0 + warp_m * 64 + mi * 16 + groupID;
        float* r0 = out + (size_t)gm * NDIM;
        float* r1 = r0 + (size_t)8 * NDIM;
        #pragma unroll
        for (int ni = 0; ni < 8; ni++) {
            const int gn = ncol0 + ni * 8 + tig * 2;
            float2 v0, v1;
            v0.x = fmaf(acc[mi][ni][0], sc2[ni].x, bi2[ni].x);
            v0.y = fmaf(acc[mi][ni][1], sc2[ni].y, bi2[ni].y);
            v1.x = fmaf(acc[mi][ni][2], sc2[ni].x, bi2[ni].x);
            v1.y = fmaf(acc[mi][ni][3], sc2[ni].y, bi2[ni].y);
            *reinterpret_cast<float2*>(r0 + gn) = v0;
            *reinterpret_cast<float2*>(r1 + gn) = v1;
        }
    }
}

// ===================== host side =====================
extern "C" void kernel_launch(void* const* d_in, const int* in_sizes, int n_in,
                              void* d_out, int out_size) {
    const float* x   = (const float*)d_in[0];
    const void*  w   = d_in[1];
    const float* sc  = (const float*)d_in[2];
    const float* bi  = (const float*)d_in[3];
    float*       out = (float*)d_out;

    // single merged prep launch: x-convert + (self-probing) w-convert
    prep_kernel<<<NBX + NBW, PREP_TPB>>>(x, w);

    cudaFuncSetAttribute(gemm_hmma_kernel,
                         cudaFuncAttributeMaxDynamicSharedMemorySize, SMEM_TOTAL);

    dim3 grid(NDIM / BN, MDIM / BM);   // (16, 64) = 1024 CTAs
    gemm_hmma_kernel<<<grid, NTHREADS, SMEM_TOTAL>>>(sc, bi, out);
}